// round 4
// baseline (speedup 1.0000x reference)
#include <cuda_runtime.h>
#include <cuda_fp16.h>
#include <cstdint>

#define Bz 4
#define Sq 4096
#define Dd 1024
#define MS (Bz * Sq)

typedef __half fp16;

// ---------------- scratch (device globals; no allocations allowed) --------
__device__ fp16 g_Xh[(size_t)MS * Dd], g_Xl[(size_t)MS * Dd];
__device__ fp16 g_Wh[3][Dd * Dd],      g_Wl[3][Dd * Dd];
__device__ fp16 g_Qh[(size_t)MS * Dd], g_Ql[(size_t)MS * Dd];
__device__ fp16 g_Kh[(size_t)MS * Dd], g_Kl[(size_t)MS * Dd];
__device__ fp16 g_Vh[(size_t)MS * Dd], g_Vl[(size_t)MS * Dd];
__device__ fp16 g_Vth[(size_t)MS * Dd], g_Vtl[(size_t)MS * Dd];  // [b][d][s]
__device__ float g_S[(size_t)Bz * Sq * Sq];                      // raw scores
__device__ fp16 g_Ph[(size_t)Bz * Sq * Sq], g_Pl[(size_t)Bz * Sq * Sq];

// =========================== PTX helpers ==================================
__device__ __forceinline__ uint32_t smem_u32(const void* p) {
    uint32_t a;
    asm("{ .reg .u64 t; cvta.to.shared.u64 t, %1; cvt.u32.u64 %0, t; }"
        : "=r"(a) : "l"(p));
    return a;
}
__device__ __forceinline__ void cp16(uint32_t s, const void* g) {
    asm volatile("cp.async.cg.shared.global [%0], [%1], 16;" :: "r"(s), "l"(g));
}
__device__ __forceinline__ void cp_commit() {
    asm volatile("cp.async.commit_group;" ::: "memory");
}
__device__ __forceinline__ void cp_wait1() {
    asm volatile("cp.async.wait_group 1;" ::: "memory");
}
__device__ __forceinline__ void ldm_x4(uint32_t a, uint32_t& r0, uint32_t& r1,
                                       uint32_t& r2, uint32_t& r3) {
    asm volatile("ldmatrix.sync.aligned.m8n8.x4.shared.b16 {%0,%1,%2,%3}, [%4];"
                 : "=r"(r0), "=r"(r1), "=r"(r2), "=r"(r3) : "r"(a));
}
__device__ __forceinline__ void mma_f16(float (&c)[4],
                                        const uint32_t (&a)[4],
                                        uint32_t b0, uint32_t b1) {
    asm volatile("mma.sync.aligned.m16n8k16.row.col.f32.f16.f16.f32 "
                 "{%0,%1,%2,%3}, {%4,%5,%6,%7}, {%8,%9}, {%0,%1,%2,%3};"
                 : "+f"(c[0]), "+f"(c[1]), "+f"(c[2]), "+f"(c[3])
                 : "r"(a[0]), "r"(a[1]), "r"(a[2]), "r"(a[3]), "r"(b0), "r"(b1));
}

// =========================== GEMM core ====================================
// C[128,256] = A[128,kLen] * B[256,kLen]^T, both K-major fp16 hi/lo planes.
// 256 threads; warp grid 2(M) x 4(N); warp tile 64x64; KC=64; 2-stage cp.async.
#define KC 64
#define PL_AL 16384
#define PL_BH 32768
#define PL_BL 65536
#define STAGE_BYTES 98304
#define SMEM_BYTES (2 * STAGE_BYTES)   // 196608

__device__ __forceinline__ void stage_copy(uint32_t sb, int tid,
    const fp16* __restrict__ Ah, const fp16* __restrict__ Al, int lda,
    const fp16* __restrict__ Bh, const fp16* __restrict__ Bl, int ldb, int k0)
{
#pragma unroll
    for (int i = 0; i < 4; i++) {           // A planes: 128 rows x 8 chunks
        int q = tid + (i << 8);
        int m = q >> 3, c = q & 7;
        uint32_t so = (uint32_t)(m * 128 + ((c ^ (m & 7)) << 4));
        size_t ga = (size_t)m * lda + k0 + c * 8;
        cp16(sb + so,         Ah + ga);
        cp16(sb + PL_AL + so, Al + ga);
    }
#pragma unroll
    for (int i = 0; i < 8; i++) {           // B planes: 256 rows x 8 chunks
        int q = tid + (i << 8);
        int m = q >> 3, c = q & 7;
        uint32_t so = (uint32_t)(m * 128 + ((c ^ (m & 7)) << 4));
        size_t gb = (size_t)m * ldb + k0 + c * 8;
        cp16(sb + PL_BH + so, Bh + gb);
        cp16(sb + PL_BL + so, Bl + gb);
    }
}

// MODE: 0 = split fp16 out (hi/lo planes), 1 = fp32 out with scale
template <int MODE>
__device__ __forceinline__ void gemm_core(
    const fp16* __restrict__ Ah, const fp16* __restrict__ Al, int lda,
    const fp16* __restrict__ Bh, const fp16* __restrict__ Bl, int ldb,
    int kLen,
    float* __restrict__ Cf, fp16* __restrict__ Ch, fp16* __restrict__ Cl,
    int ldc, float scale)
{
    extern __shared__ char dyn[];
    const uint32_t sbase = smem_u32(dyn);
    const int tid = threadIdx.x;
    const int l = tid & 31, wid = tid >> 5;
    const int wm = wid & 1, wn = wid >> 1;
    const int kT = kLen >> 6;

    float acc[4][8][4];
#pragma unroll
    for (int i = 0; i < 4; i++)
#pragma unroll
        for (int j = 0; j < 8; j++)
#pragma unroll
            for (int k = 0; k < 4; k++) acc[i][j][k] = 0.f;

    stage_copy(sbase, tid, Ah, Al, lda, Bh, Bl, ldb, 0);
    cp_commit();
    if (kT > 1) stage_copy(sbase + STAGE_BYTES, tid, Ah, Al, lda, Bh, Bl, ldb, KC);
    cp_commit();

    const int arow = l & 15;
    const int c0A  = (l >> 4) & 1;
    const int brow = (l & 7) + ((l & 16) >> 1);
    const int c0B  = (l >> 3) & 1;
    const int lm7  = l & 7;

    for (int kt = 0; kt < kT; kt++) {
        cp_wait1();
        __syncthreads();
        const uint32_t sb = sbase + (kt & 1) * STAGE_BYTES;

#pragma unroll
        for (int k16 = 0; k16 < 4; k16++) {
            uint32_t ah[4][4], al_[4][4];
#pragma unroll
            for (int tm = 0; tm < 4; tm++) {
                uint32_t off = (uint32_t)((wm * 64 + tm * 16 + arow) * 128)
                             + (uint32_t)(((2 * k16 + c0A) ^ lm7) << 4);
                ldm_x4(sb + off,         ah[tm][0],  ah[tm][1],  ah[tm][2],  ah[tm][3]);
                ldm_x4(sb + PL_AL + off, al_[tm][0], al_[tm][1], al_[tm][2], al_[tm][3]);
            }
#pragma unroll
            for (int np = 0; np < 4; np++) {
                uint32_t offB = (uint32_t)((wn * 64 + np * 16 + brow) * 128)
                              + (uint32_t)(((2 * k16 + c0B) ^ lm7) << 4);
                uint32_t h0, h1, h2, h3, q0, q1, q2, q3;
                ldm_x4(sb + PL_BH + offB, h0, h1, h2, h3);
                ldm_x4(sb + PL_BL + offB, q0, q1, q2, q3);
#pragma unroll
                for (int tm = 0; tm < 4; tm++) {
                    mma_f16(acc[tm][np * 2],     ah[tm],  h0, h1);
                    mma_f16(acc[tm][np * 2],     ah[tm],  q0, q1);
                    mma_f16(acc[tm][np * 2],     al_[tm], h0, h1);
                    mma_f16(acc[tm][np * 2 + 1], ah[tm],  h2, h3);
                    mma_f16(acc[tm][np * 2 + 1], ah[tm],  q2, q3);
                    mma_f16(acc[tm][np * 2 + 1], al_[tm], h2, h3);
                }
            }
        }
        __syncthreads();
        if (kt + 2 < kT)
            stage_copy(sbase + (kt & 1) * STAGE_BYTES, tid, Ah, Al, lda,
                       Bh, Bl, ldb, (kt + 2) * KC);
        cp_commit();
    }

    // epilogue
    const int g = l >> 2, tg = l & 3;
#pragma unroll
    for (int tm = 0; tm < 4; tm++) {
        const int r0 = wm * 64 + tm * 16 + g;
#pragma unroll
        for (int tn = 0; tn < 8; tn++) {
            const int col = wn * 64 + tn * 8 + tg * 2;
            const float* a = acc[tm][tn];
            if (MODE == 1) {
                *(float2*)(Cf + (size_t)r0 * ldc + col) =
                    make_float2(a[0] * scale, a[1] * scale);
                *(float2*)(Cf + (size_t)(r0 + 8) * ldc + col) =
                    make_float2(a[2] * scale, a[3] * scale);
            } else {
#pragma unroll
                for (int h = 0; h < 2; h++) {
                    float x0 = a[2 * h], x1 = a[2 * h + 1];
                    fp16 h0 = __float2half_rn(x0);
                    fp16 h1 = __float2half_rn(x1);
                    fp16 l0 = __float2half_rn(x0 - __half2float(h0));
                    fp16 l1 = __float2half_rn(x1 - __half2float(h1));
                    size_t o = (size_t)(r0 + 8 * h) * ldc + col;
                    *(__half2*)(Ch + o) = __halves2half2(h0, h1);
                    *(__half2*)(Cl + o) = __halves2half2(l0, l1);
                }
            }
        }
    }
}

// =========================== GEMM kernels =================================
__global__ __launch_bounds__(256, 1)
void k_qkv()
{
    const int z = blockIdx.z;
    fp16* Oh = (z == 0) ? g_Qh : (z == 1) ? g_Kh : g_Vh;
    fp16* Ol = (z == 0) ? g_Ql : (z == 1) ? g_Kl : g_Vl;
    const size_t m0 = (size_t)blockIdx.y * 128;
    const size_t n0 = (size_t)blockIdx.x * 256;
    gemm_core<0>(g_Xh + m0 * Dd, g_Xl + m0 * Dd, Dd,
                 g_Wh[z] + n0 * Dd, g_Wl[z] + n0 * Dd, Dd, Dd,
                 nullptr, Oh + m0 * Dd + n0, Ol + m0 * Dd + n0, Dd, 1.0f);
}

__global__ __launch_bounds__(256, 1)
void k_scores()
{
    const int kt = blockIdx.x, qt = blockIdx.y, b = blockIdx.z;
    if (2 * kt > qt) return;   // key tile fully above causal diagonal
    const size_t qo = (size_t)b * Sq * Dd + (size_t)qt * 128 * Dd;
    const size_t ko = (size_t)b * Sq * Dd + (size_t)kt * 256 * Dd;
    gemm_core<1>(g_Qh + qo, g_Ql + qo, Dd,
                 g_Kh + ko, g_Kl + ko, Dd, Dd,
                 g_S + (size_t)b * Sq * Sq + (size_t)qt * 128 * Sq + kt * 256,
                 nullptr, nullptr, Sq, 0.03125f);
}

__global__ __launch_bounds__(256, 1)
void k_pv(float* __restrict__ out)
{
    const int b = blockIdx.z;
    const size_t m0 = (size_t)blockIdx.y * 128;
    const size_t n0 = (size_t)blockIdx.x * 256;
    const size_t po = (size_t)b * Sq * Sq + m0 * Sq;
    const size_t vo = (size_t)b * Sq * Dd + n0 * Sq;
    gemm_core<1>(g_Ph + po, g_Pl + po, Sq,
                 g_Vth + vo, g_Vtl + vo, Sq, (int)(m0 + 128),
                 out + (size_t)b * Sq * Dd + m0 * Dd + n0,
                 nullptr, nullptr, Dd, 1.0f);
}

// =========================== aux kernels ==================================
__global__ __launch_bounds__(256)
void k_split(const float* __restrict__ s, fp16* __restrict__ h,
             fp16* __restrict__ l, int n4)
{
    int i = blockIdx.x * 256 + threadIdx.x;
    if (i >= n4) return;
    float4 v = ((const float4*)s)[i];
    fp16 h0 = __float2half_rn(v.x), h1 = __float2half_rn(v.y);
    fp16 h2 = __float2half_rn(v.z), h3 = __float2half_rn(v.w);
    fp16 l0 = __float2half_rn(v.x - __half2float(h0));
    fp16 l1 = __float2half_rn(v.y - __half2float(h1));
    fp16 l2 = __float2half_rn(v.z - __half2float(h2));
    fp16 l3 = __float2half_rn(v.w - __half2float(h3));
    ((__half2*)h)[2 * i]     = __halves2half2(h0, h1);
    ((__half2*)h)[2 * i + 1] = __halves2half2(h2, h3);
    ((__half2*)l)[2 * i]     = __halves2half2(l0, l1);
    ((__half2*)l)[2 * i + 1] = __halves2half2(l2, l3);
}

__global__ void k_vtrans()
{
    __shared__ fp16 t[32][33];
    const int zz = blockIdx.z, b = zz >> 1, pl = zz & 1;
    const fp16* V = (pl ? g_Vl : g_Vh) + (size_t)b * Sq * Dd;
    fp16*       T = (pl ? g_Vtl : g_Vth) + (size_t)b * Sq * Dd;
    const int s0 = blockIdx.x * 32, d0 = blockIdx.y * 32;
    const int x = threadIdx.x, y = threadIdx.y;
#pragma unroll
    for (int i = 0; i < 32; i += 8)
        t[y + i][x] = V[(size_t)(s0 + y + i) * Dd + d0 + x];
    __syncthreads();
#pragma unroll
    for (int i = 0; i < 32; i += 8)
        T[(size_t)(d0 + y + i) * Sq + s0 + x] = t[x][y + i];
}

__global__ __launch_bounds__(256)
void k_softmax()
{
    const int q = blockIdx.x, b = blockIdx.y;
    const size_t ro = ((size_t)b * Sq + q) * Sq;
    const float* row = g_S + ro;
    const int len = q + 1;
    const int tid = threadIdx.x;

    __shared__ float buf[Sq];
    __shared__ float red[8];
    __shared__ float bval;

    float m = -3.4e38f;
    for (int i = tid; i < len; i += 256) {
        float v = row[i];
        buf[i] = v;
        m = fmaxf(m, v);
    }
#pragma unroll
    for (int o = 16; o > 0; o >>= 1) m = fmaxf(m, __shfl_xor_sync(0xffffffffu, m, o));
    if ((tid & 31) == 0) red[tid >> 5] = m;
    __syncthreads();
    if (tid == 0) {
        float mm = red[0];
#pragma unroll
        for (int w = 1; w < 8; w++) mm = fmaxf(mm, red[w]);
        bval = mm;
    }
    __syncthreads();
    m = bval;

    float s = 0.f;
    for (int i = tid; i < len; i += 256) {
        float e = __expf(buf[i] - m);
        buf[i] = e;
        s += e;
    }
#pragma unroll
    for (int o = 16; o > 0; o >>= 1) s += __shfl_xor_sync(0xffffffffu, s, o);
    __syncthreads();
    if ((tid & 31) == 0) red[tid >> 5] = s;
    __syncthreads();
    if (tid == 0) {
        float ss = red[0];
#pragma unroll
        for (int w = 1; w < 8; w++) ss += red[w];
        bval = 1.f / ss;
    }
    __syncthreads();
    const float inv = bval;

    for (int i = tid; i < len; i += 256) {
        float p = buf[i] * inv;
        fp16 h = __float2half_rn(p);
        fp16 lo = __float2half_rn(p - __half2float(h));
        g_Ph[ro + i] = h;
        g_Pl[ro + i] = lo;
    }
    const int padlen = ((q >> 7) + 1) << 7;
    for (int i = len + tid; i < padlen; i += 256) {
        g_Ph[ro + i] = __float2half_rn(0.f);
        g_Pl[ro + i] = __float2half_rn(0.f);
    }
}

// ===========================================================================
extern "C" void kernel_launch(void* const* d_in, const int* in_sizes, int n_in,
                              void* d_out, int out_size)
{
    const float* X  = (const float*)d_in[0];
    const float* Wq = (const float*)d_in[1];
    const float* Wk = (const float*)d_in[2];
    const float* Wv = (const float*)d_in[3];
    float* out = (float*)d_out;

    cudaFuncSetAttribute(k_qkv,    cudaFuncAttributeMaxDynamicSharedMemorySize, SMEM_BYTES);
    cudaFuncSetAttribute(k_scores, cudaFuncAttributeMaxDynamicSharedMemorySize, SMEM_BYTES);
    cudaFuncSetAttribute(k_pv,     cudaFuncAttributeMaxDynamicSharedMemorySize, SMEM_BYTES);

    fp16 *xh, *xl, *wh, *wl;
    cudaGetSymbolAddress((void**)&xh, g_Xh);
    cudaGetSymbolAddress((void**)&xl, g_Xl);
    cudaGetSymbolAddress((void**)&wh, g_Wh);
    cudaGetSymbolAddress((void**)&wl, g_Wl);

    k_split<<<(MS * Dd / 4 + 255) / 256, 256>>>(X, xh, xl, MS * Dd / 4);
    k_split<<<(Dd * Dd / 4 + 255) / 256, 256>>>(Wq, wh,               wl,               Dd * Dd / 4);
    k_split<<<(Dd * Dd / 4 + 255) / 256, 256>>>(Wk, wh + Dd * Dd,     wl + Dd * Dd,     Dd * Dd / 4);
    k_split<<<(Dd * Dd / 4 + 255) / 256, 256>>>(Wv, wh + 2 * Dd * Dd, wl + 2 * Dd * Dd, Dd * Dd / 4);

    k_qkv<<<dim3(Dd / 256, MS / 128, 3), 256, SMEM_BYTES>>>();
    k_vtrans<<<dim3(Sq / 32, Dd / 32, Bz * 2), dim3(32, 8)>>>();
    k_scores<<<dim3(Sq / 256, Sq / 128, Bz), 256, SMEM_BYTES>>>();
    k_softmax<<<dim3(Sq, Bz), 256>>>();
    k_pv<<<dim3(Dd / 256, Sq / 128, Bz), 256, SMEM_BYTES>>>(out);
}

// round 5
// speedup vs baseline: 1.0355x; 1.0355x over previous
#include <cuda_runtime.h>
#include <cuda_fp16.h>
#include <cstdint>

#define Bz 4
#define Sq 4096
#define Dd 1024
#define MS (Bz * Sq)

typedef __half fp16;

// ---------------- scratch (device globals; no allocations allowed) --------
__device__ fp16 g_Xh[(size_t)MS * Dd], g_Xl[(size_t)MS * Dd];
__device__ fp16 g_Wh[3][Dd * Dd],      g_Wl[3][Dd * Dd];
__device__ fp16 g_Qh[(size_t)MS * Dd], g_Ql[(size_t)MS * Dd];
__device__ fp16 g_Kh[(size_t)MS * Dd], g_Kl[(size_t)MS * Dd];
__device__ fp16 g_Vh[(size_t)MS * Dd], g_Vl[(size_t)MS * Dd];
__device__ fp16 g_Vth[(size_t)MS * Dd], g_Vtl[(size_t)MS * Dd];  // [b][d][s]
__device__ float g_S[(size_t)Bz * Sq * Sq];                      // raw scores
__device__ fp16 g_Ph[(size_t)Bz * Sq * Sq], g_Pl[(size_t)Bz * Sq * Sq];

// =========================== PTX helpers ==================================
__device__ __forceinline__ uint32_t smem_u32(const void* p) {
    uint32_t a;
    asm("{ .reg .u64 t; cvta.to.shared.u64 t, %1; cvt.u32.u64 %0, t; }"
        : "=r"(a) : "l"(p));
    return a;
}
__device__ __forceinline__ void cp16(uint32_t s, const void* g) {
    asm volatile("cp.async.cg.shared.global [%0], [%1], 16;" :: "r"(s), "l"(g));
}
__device__ __forceinline__ void cp_commit() {
    asm volatile("cp.async.commit_group;" ::: "memory");
}
__device__ __forceinline__ void cp_wait1() {
    asm volatile("cp.async.wait_group 1;" ::: "memory");
}
__device__ __forceinline__ void ldm_x4(uint32_t a, uint32_t& r0, uint32_t& r1,
                                       uint32_t& r2, uint32_t& r3) {
    asm volatile("ldmatrix.sync.aligned.m8n8.x4.shared.b16 {%0,%1,%2,%3}, [%4];"
                 : "=r"(r0), "=r"(r1), "=r"(r2), "=r"(r3) : "r"(a));
}
__device__ __forceinline__ void mma_f16(float (&c)[4],
                                        const uint32_t (&a)[4],
                                        uint32_t b0, uint32_t b1) {
    asm volatile("mma.sync.aligned.m16n8k16.row.col.f32.f16.f16.f32 "
                 "{%0,%1,%2,%3}, {%4,%5,%6,%7}, {%8,%9}, {%0,%1,%2,%3};"
                 : "+f"(c[0]), "+f"(c[1]), "+f"(c[2]), "+f"(c[3])
                 : "r"(a[0]), "r"(a[1]), "r"(a[2]), "r"(a[3]), "r"(b0), "r"(b1));
}

// =========================== GEMM core ====================================
// C[128,128] = A[128,kLen] * B[128,kLen]^T, both K-major fp16 hi/lo planes.
// 256 threads; warp grid 2(M) x 4(N); warp tile 64x32; KC=32; 3-stage cp.async.
// 32KB stage (rows are 64B; swizzle: chunk ^= (row>>1)&3) -> 96KB smem,
// 2 CTAs/SM for latency hiding.
#define KC 32
#define PL_AL 8192
#define PL_BH 16384
#define PL_BL 24576
#define STAGE_BYTES 32768
#define SMEM_BYTES (3 * STAGE_BYTES)   // 98304

__device__ __forceinline__ void stage_copy(uint32_t sb, int tid,
    const fp16* __restrict__ Ah, const fp16* __restrict__ Al, int lda,
    const fp16* __restrict__ Bh, const fp16* __restrict__ Bl, int ldb, int k0)
{
    // each plane: 128 rows x 4 chunks(16B) = 512 cp16; 2 iters of 256 threads
#pragma unroll
    for (int i = 0; i < 2; i++) {
        int q = tid + (i << 8);
        int m = q >> 2, c = q & 3;
        uint32_t so = (uint32_t)(m * 64 + ((c ^ ((m >> 1) & 3)) << 4));
        size_t ga = (size_t)m * lda + k0 + c * 8;
        size_t gb = (size_t)m * ldb + k0 + c * 8;
        cp16(sb + so,         Ah + ga);
        cp16(sb + PL_AL + so, Al + ga);
        cp16(sb + PL_BH + so, Bh + gb);
        cp16(sb + PL_BL + so, Bl + gb);
    }
}

// MODE: 0 = split fp16 out (hi/lo planes), 1 = fp32 out with scale
template <int MODE>
__device__ __forceinline__ void gemm_core(
    const fp16* __restrict__ Ah, const fp16* __restrict__ Al, int lda,
    const fp16* __restrict__ Bh, const fp16* __restrict__ Bl, int ldb,
    int kLen,
    float* __restrict__ Cf, fp16* __restrict__ Ch, fp16* __restrict__ Cl,
    int ldc, float scale)
{
    extern __shared__ char dyn[];
    const uint32_t sbase = smem_u32(dyn);
    const int tid = threadIdx.x;
    const int l = tid & 31, wid = tid >> 5;
    const int wm = wid & 1, wn = wid >> 1;
    const int kT = kLen >> 5;   // K tiles of 32

    float acc[4][4][4];
#pragma unroll
    for (int i = 0; i < 4; i++)
#pragma unroll
        for (int j = 0; j < 4; j++)
#pragma unroll
            for (int k = 0; k < 4; k++) acc[i][j][k] = 0.f;

    stage_copy(sbase, tid, Ah, Al, lda, Bh, Bl, ldb, 0);
    cp_commit();
    if (kT > 1) stage_copy(sbase + STAGE_BYTES, tid, Ah, Al, lda, Bh, Bl, ldb, KC);
    cp_commit();

    const int arow = l & 15;            // A: row within 16-row frag
    const int c0A  = (l >> 4) & 1;      // A: k-half
    const int brow = (l & 7) + ((l & 16) >> 1);   // B: n row
    const int c0B  = (l >> 3) & 1;      // B: k-half
    const int aRowBase = wm * 64 + arow;
    const int bRowBase = wn * 32 + brow;

    int slot = 0;
    for (int kt = 0; kt < kT; kt++) {
        cp_wait1();
        __syncthreads();
        if (kt + 2 < kT) {
            int ps = slot + 2; if (ps >= 3) ps -= 3;
            stage_copy(sbase + ps * STAGE_BYTES, tid, Ah, Al, lda, Bh, Bl, ldb,
                       (kt + 2) * KC);
        }
        cp_commit();

        const uint32_t sb = sbase + slot * STAGE_BYTES;
        if (++slot == 3) slot = 0;

#pragma unroll
        for (int k16 = 0; k16 < 2; k16++) {
            // B fragments first (shared across tm)
            uint32_t bh[4][2], bl_[4][2];
#pragma unroll
            for (int pr = 0; pr < 2; pr++) {
                int row = bRowBase + pr * 16;
                uint32_t off = (uint32_t)(row * 64)
                             + (uint32_t)((((2 * k16 + c0B) ^ ((row >> 1) & 3))) << 4);
                uint32_t r0, r1, r2, r3;
                ldm_x4(sb + PL_BH + off, r0, r1, r2, r3);
                bh[pr * 2][0] = r0; bh[pr * 2][1] = r1;
                bh[pr * 2 + 1][0] = r2; bh[pr * 2 + 1][1] = r3;
                ldm_x4(sb + PL_BL + off, r0, r1, r2, r3);
                bl_[pr * 2][0] = r0; bl_[pr * 2][1] = r1;
                bl_[pr * 2 + 1][0] = r2; bl_[pr * 2 + 1][1] = r3;
            }
#pragma unroll
            for (int tm = 0; tm < 4; tm++) {
                int row = aRowBase + tm * 16;
                uint32_t off = (uint32_t)(row * 64)
                             + (uint32_t)((((2 * k16 + c0A) ^ ((row >> 1) & 3))) << 4);
                uint32_t ah[4], al_[4];
                ldm_x4(sb + off,         ah[0],  ah[1],  ah[2],  ah[3]);
                ldm_x4(sb + PL_AL + off, al_[0], al_[1], al_[2], al_[3]);
#pragma unroll
                for (int tn = 0; tn < 4; tn++) {
                    mma_f16(acc[tm][tn], ah,  bh[tn][0],  bh[tn][1]);
                    mma_f16(acc[tm][tn], ah,  bl_[tn][0], bl_[tn][1]);
                    mma_f16(acc[tm][tn], al_, bh[tn][0],  bh[tn][1]);
                }
            }
        }
    }

    // epilogue
    const int g = l >> 2, tg = l & 3;
#pragma unroll
    for (int tm = 0; tm < 4; tm++) {
        const int r0 = wm * 64 + tm * 16 + g;
#pragma unroll
        for (int tn = 0; tn < 4; tn++) {
            const int col = wn * 32 + tn * 8 + tg * 2;
            const float* a = acc[tm][tn];
            if (MODE == 1) {
                *(float2*)(Cf + (size_t)r0 * ldc + col) =
                    make_float2(a[0] * scale, a[1] * scale);
                *(float2*)(Cf + (size_t)(r0 + 8) * ldc + col) =
                    make_float2(a[2] * scale, a[3] * scale);
            } else {
#pragma unroll
                for (int h = 0; h < 2; h++) {
                    float x0 = a[2 * h], x1 = a[2 * h + 1];
                    fp16 h0 = __float2half_rn(x0);
                    fp16 h1 = __float2half_rn(x1);
                    fp16 l0 = __float2half_rn(x0 - __half2float(h0));
                    fp16 l1 = __float2half_rn(x1 - __half2float(h1));
                    size_t o = (size_t)(r0 + 8 * h) * ldc + col;
                    *(__half2*)(Ch + o) = __halves2half2(h0, h1);
                    *(__half2*)(Cl + o) = __halves2half2(l0, l1);
                }
            }
        }
    }
}

// =========================== GEMM kernels =================================
__global__ __launch_bounds__(256, 2)
void k_qkv()
{
    const int z = blockIdx.z;
    fp16* Oh = (z == 0) ? g_Qh : (z == 1) ? g_Kh : g_Vh;
    fp16* Ol = (z == 0) ? g_Ql : (z == 1) ? g_Kl : g_Vl;
    const size_t m0 = (size_t)blockIdx.y * 128;
    const size_t n0 = (size_t)blockIdx.x * 128;
    gemm_core<0>(g_Xh + m0 * Dd, g_Xl + m0 * Dd, Dd,
                 g_Wh[z] + n0 * Dd, g_Wl[z] + n0 * Dd, Dd, Dd,
                 nullptr, Oh + m0 * Dd + n0, Ol + m0 * Dd + n0, Dd, 1.0f);
}

__global__ __launch_bounds__(256, 2)
void k_scores()
{
    const int kt = blockIdx.x, qt = blockIdx.y, b = blockIdx.z;
    if (kt > qt) return;
    const size_t qo = (size_t)b * Sq * Dd + (size_t)qt * 128 * Dd;
    const size_t ko = (size_t)b * Sq * Dd + (size_t)kt * 128 * Dd;
    gemm_core<1>(g_Qh + qo, g_Ql + qo, Dd,
                 g_Kh + ko, g_Kl + ko, Dd, Dd,
                 g_S + (size_t)b * Sq * Sq + (size_t)qt * 128 * Sq + kt * 128,
                 nullptr, nullptr, Sq, 0.03125f);
}

__global__ __launch_bounds__(256, 2)
void k_pv(float* __restrict__ out)
{
    const int b = blockIdx.z;
    const size_t m0 = (size_t)blockIdx.y * 128;
    const size_t n0 = (size_t)blockIdx.x * 128;
    const size_t po = (size_t)b * Sq * Sq + m0 * Sq;
    const size_t vo = (size_t)b * Sq * Dd + n0 * Sq;
    gemm_core<1>(g_Ph + po, g_Pl + po, Sq,
                 g_Vth + vo, g_Vtl + vo, Sq, (int)(m0 + 128),
                 out + (size_t)b * Sq * Dd + m0 * Dd + n0,
                 nullptr, nullptr, Dd, 1.0f);
}

// =========================== aux kernels ==================================
__global__ __launch_bounds__(256)
void k_splitX(const float* __restrict__ s, fp16* __restrict__ h,
              fp16* __restrict__ l)
{
    int i = blockIdx.x * 256 + threadIdx.x;
    float4 v = ((const float4*)s)[i];
    fp16 h0 = __float2half_rn(v.x), h1 = __float2half_rn(v.y);
    fp16 h2 = __float2half_rn(v.z), h3 = __float2half_rn(v.w);
    fp16 l0 = __float2half_rn(v.x - __half2float(h0));
    fp16 l1 = __float2half_rn(v.y - __half2float(h1));
    fp16 l2 = __float2half_rn(v.z - __half2float(h2));
    fp16 l3 = __float2half_rn(v.w - __half2float(h3));
    ((__half2*)h)[2 * i]     = __halves2half2(h0, h1);
    ((__half2*)h)[2 * i + 1] = __halves2half2(h2, h3);
    ((__half2*)l)[2 * i]     = __halves2half2(l0, l1);
    ((__half2*)l)[2 * i + 1] = __halves2half2(l2, l3);
}

__global__ __launch_bounds__(256)
void k_splitW(const float* __restrict__ wq, const float* __restrict__ wk,
              const float* __restrict__ wv)
{
    const int z = blockIdx.y;
    const float* s = (z == 0) ? wq : (z == 1) ? wk : wv;
    fp16* h = g_Wh[z];
    fp16* l = g_Wl[z];
    int i = blockIdx.x * 256 + threadIdx.x;
    float4 v = ((const float4*)s)[i];
    fp16 h0 = __float2half_rn(v.x), h1 = __float2half_rn(v.y);
    fp16 h2 = __float2half_rn(v.z), h3 = __float2half_rn(v.w);
    fp16 l0 = __float2half_rn(v.x - __half2float(h0));
    fp16 l1 = __float2half_rn(v.y - __half2float(h1));
    fp16 l2 = __float2half_rn(v.z - __half2float(h2));
    fp16 l3 = __float2half_rn(v.w - __half2float(h3));
    ((__half2*)h)[2 * i]     = __halves2half2(h0, h1);
    ((__half2*)h)[2 * i + 1] = __halves2half2(h2, h3);
    ((__half2*)l)[2 * i]     = __halves2half2(l0, l1);
    ((__half2*)l)[2 * i + 1] = __halves2half2(l2, l3);
}

__global__ void k_vtrans()
{
    __shared__ fp16 t[32][33];
    const int zz = blockIdx.z, b = zz >> 1, pl = zz & 1;
    const fp16* V = (pl ? g_Vl : g_Vh) + (size_t)b * Sq * Dd;
    fp16*       T = (pl ? g_Vtl : g_Vth) + (size_t)b * Sq * Dd;
    const int s0 = blockIdx.x * 32, d0 = blockIdx.y * 32;
    const int x = threadIdx.x, y = threadIdx.y;
#pragma unroll
    for (int i = 0; i < 32; i += 8)
        t[y + i][x] = V[(size_t)(s0 + y + i) * Dd + d0 + x];
    __syncthreads();
#pragma unroll
    for (int i = 0; i < 32; i += 8)
        T[(size_t)(d0 + y + i) * Sq + s0 + x] = t[x][y + i];
}

__global__ __launch_bounds__(256)
void k_softmax()
{
    const int q = blockIdx.x, b = blockIdx.y;
    const size_t ro = ((size_t)b * Sq + q) * Sq;
    const float* row = g_S + ro;
    const int len = q + 1;
    const int tid = threadIdx.x;

    __shared__ float buf[Sq];
    __shared__ float red[8];
    __shared__ float bval;

    float m = -3.4e38f;
    for (int i = tid; i < len; i += 256) {
        float v = row[i];
        buf[i] = v;
        m = fmaxf(m, v);
    }
#pragma unroll
    for (int o = 16; o > 0; o >>= 1) m = fmaxf(m, __shfl_xor_sync(0xffffffffu, m, o));
    if ((tid & 31) == 0) red[tid >> 5] = m;
    __syncthreads();
    if (tid == 0) {
        float mm = red[0];
#pragma unroll
        for (int w = 1; w < 8; w++) mm = fmaxf(mm, red[w]);
        bval = mm;
    }
    __syncthreads();
    m = bval;

    float s = 0.f;
    for (int i = tid; i < len; i += 256) {
        float e = __expf(buf[i] - m);
        buf[i] = e;
        s += e;
    }
#pragma unroll
    for (int o = 16; o > 0; o >>= 1) s += __shfl_xor_sync(0xffffffffu, s, o);
    __syncthreads();
    if ((tid & 31) == 0) red[tid >> 5] = s;
    __syncthreads();
    if (tid == 0) {
        float ss = red[0];
#pragma unroll
        for (int w = 1; w < 8; w++) ss += red[w];
        bval = 1.f / ss;
    }
    __syncthreads();
    const float inv = bval;

    for (int i = tid; i < len; i += 256) {
        float p = buf[i] * inv;
        fp16 h = __float2half_rn(p);
        fp16 lo = __float2half_rn(p - __half2float(h));
        g_Ph[ro + i] = h;
        g_Pl[ro + i] = lo;
    }
    const int padlen = ((q >> 7) + 1) << 7;
    for (int i = len + tid; i < padlen; i += 256) {
        g_Ph[ro + i] = __float2half_rn(0.f);
        g_Pl[ro + i] = __float2half_rn(0.f);
    }
}

// ===========================================================================
extern "C" void kernel_launch(void* const* d_in, const int* in_sizes, int n_in,
                              void* d_out, int out_size)
{
    const float* X  = (const float*)d_in[0];
    const float* Wq = (const float*)d_in[1];
    const float* Wk = (const float*)d_in[2];
    const float* Wv = (const float*)d_in[3];
    float* out = (float*)d_out;

    cudaFuncSetAttribute(k_qkv,    cudaFuncAttributeMaxDynamicSharedMemorySize, SMEM_BYTES);
    cudaFuncSetAttribute(k_scores, cudaFuncAttributeMaxDynamicSharedMemorySize, SMEM_BYTES);
    cudaFuncSetAttribute(k_pv,     cudaFuncAttributeMaxDynamicSharedMemorySize, SMEM_BYTES);

    fp16 *xh, *xl;
    cudaGetSymbolAddress((void**)&xh, g_Xh);
    cudaGetSymbolAddress((void**)&xl, g_Xl);

    k_splitX<<<MS * Dd / 4 / 256, 256>>>(X, xh, xl);
    k_splitW<<<dim3(Dd * Dd / 4 / 256, 3), 256>>>(Wq, Wk, Wv);

    k_qkv<<<dim3(Dd / 128, MS / 128, 3), 256, SMEM_BYTES>>>();
    k_vtrans<<<dim3(Sq / 32, Dd / 32, Bz * 2), dim3(32, 8)>>>();
    k_scores<<<dim3(Sq / 128, Sq / 128, Bz), 256, SMEM_BYTES>>>();
    k_softmax<<<dim3(Sq, Bz), 256>>>();
    k_pv<<<dim3(Dd / 128, Sq / 128, Bz), 256, SMEM_BYTES>>>(out);
}

// round 6
// speedup vs baseline: 1.4191x; 1.3705x over previous
#include <cuda_runtime.h>
#include <cuda_fp16.h>
#include <cstdint>

#define Bz 4
#define Sq 4096
#define Dd 1024
#define MS (Bz * Sq)

typedef __half fp16;

// ---------------- scratch (device globals; no allocations allowed) --------
__device__ fp16 g_Xh[(size_t)MS * Dd], g_Xl[(size_t)MS * Dd];
__device__ fp16 g_Wh[3][Dd * Dd],      g_Wl[3][Dd * Dd];
__device__ fp16 g_Qh[(size_t)MS * Dd];                    // hi only
__device__ fp16 g_Kh[(size_t)MS * Dd];                    // hi only
__device__ fp16 g_Vh[(size_t)MS * Dd], g_Vl[(size_t)MS * Dd];
__device__ fp16 g_Vth[(size_t)MS * Dd], g_Vtl[(size_t)MS * Dd];  // [b][d][s]
__device__ float g_S[(size_t)Bz * Sq * Sq];               // raw scores
__device__ fp16 g_Ph[(size_t)Bz * Sq * Sq];               // probs, hi only

// =========================== PTX helpers ==================================
__device__ __forceinline__ uint32_t smem_u32(const void* p) {
    uint32_t a;
    asm("{ .reg .u64 t; cvta.to.shared.u64 t, %1; cvt.u32.u64 %0, t; }"
        : "=r"(a) : "l"(p));
    return a;
}
__device__ __forceinline__ void cp16(uint32_t s, const void* g) {
    asm volatile("cp.async.cg.shared.global [%0], [%1], 16;" :: "r"(s), "l"(g));
}
__device__ __forceinline__ void cp_commit() {
    asm volatile("cp.async.commit_group;" ::: "memory");
}
__device__ __forceinline__ void cp_wait1() {
    asm volatile("cp.async.wait_group 1;" ::: "memory");
}
__device__ __forceinline__ void ldm_x4(uint32_t a, uint32_t& r0, uint32_t& r1,
                                       uint32_t& r2, uint32_t& r3) {
    asm volatile("ldmatrix.sync.aligned.m8n8.x4.shared.b16 {%0,%1,%2,%3}, [%4];"
                 : "=r"(r0), "=r"(r1), "=r"(r2), "=r"(r3) : "r"(a));
}
__device__ __forceinline__ void mma_f16(float (&c)[4],
                                        const uint32_t (&a)[4],
                                        uint32_t b0, uint32_t b1) {
    asm volatile("mma.sync.aligned.m16n8k16.row.col.f32.f16.f16.f32 "
                 "{%0,%1,%2,%3}, {%4,%5,%6,%7}, {%8,%9}, {%0,%1,%2,%3};"
                 : "+f"(c[0]), "+f"(c[1]), "+f"(c[2]), "+f"(c[3])
                 : "r"(a[0]), "r"(a[1]), "r"(a[2]), "r"(a[3]), "r"(b0), "r"(b1));
}

// =========================== GEMM core ====================================
// C[128,128] = A[128,kLen] * B[128,kLen]^T, K-major fp16 planes, KC=64,
// 3-stage cp.async, 256 threads, warp grid 2(M) x 4(N), warp tile 64x32.
// TERMS=3: Ah*Bh + Ah*Bl + Al*Bh   (planes Ah,Al,Bh,Bl)
// TERMS=2: Ah*Bh + Ah*Bl           (planes Ah,Bh,Bl)
// TERMS=1: Ah*Bh                   (planes Ah,Bh)
#define KC 64
#define PLANE_B 16384   // one plane: 128 rows x 128 bytes

template <int TERMS>
__device__ __forceinline__ void stage_copy(uint32_t sb, int tid,
    const fp16* __restrict__ Ah, const fp16* __restrict__ Al, int lda,
    const fp16* __restrict__ Bh, const fp16* __restrict__ Bl, int ldb, int k0)
{
    const uint32_t PB_H = (TERMS == 3) ? 2 * PLANE_B : PLANE_B;
#pragma unroll
    for (int i = 0; i < 4; i++) {
        int q = tid + (i << 8);
        int m = q >> 3, c = q & 7;
        uint32_t so = (uint32_t)(m * 128 + ((c ^ (m & 7)) << 4));
        size_t ga = (size_t)m * lda + k0 + c * 8;
        size_t gb = (size_t)m * ldb + k0 + c * 8;
        cp16(sb + so, Ah + ga);
        if (TERMS == 3) cp16(sb + PLANE_B + so, Al + ga);
        cp16(sb + PB_H + so, Bh + gb);
        if (TERMS >= 2) cp16(sb + PB_H + PLANE_B + so, Bl + gb);
    }
}

// mode: 0 = fp16 single plane (Ch); 1 = fp32 with scale (Cf); 2 = fp16 hi/lo
template <int TERMS>
__device__ __forceinline__ void gemm_core(
    const fp16* __restrict__ Ah, const fp16* __restrict__ Al, int lda,
    const fp16* __restrict__ Bh, const fp16* __restrict__ Bl, int ldb,
    int kLen,
    float* __restrict__ Cf, fp16* __restrict__ Ch, fp16* __restrict__ Cl,
    int ldc, float scale, int mode)
{
    const uint32_t PB_H = (TERMS == 3) ? 2 * PLANE_B : PLANE_B;
    const uint32_t STAGE = (uint32_t)(TERMS + 1) * PLANE_B;

    extern __shared__ char dyn[];
    const uint32_t sbase = smem_u32(dyn);
    const int tid = threadIdx.x;
    const int l = tid & 31, wid = tid >> 5;
    const int wm = wid & 1, wn = wid >> 1;
    const int kT = kLen >> 6;   // K tiles of 64

    float acc[4][4][4];
#pragma unroll
    for (int i = 0; i < 4; i++)
#pragma unroll
        for (int j = 0; j < 4; j++)
#pragma unroll
            for (int k = 0; k < 4; k++) acc[i][j][k] = 0.f;

    stage_copy<TERMS>(sbase, tid, Ah, Al, lda, Bh, Bl, ldb, 0);
    cp_commit();
    if (kT > 1) stage_copy<TERMS>(sbase + STAGE, tid, Ah, Al, lda, Bh, Bl, ldb, KC);
    cp_commit();

    const int arow = l & 15;
    const int c0A  = (l >> 4) & 1;
    const int brow = (l & 7) + ((l & 16) >> 1);
    const int c0B  = (l >> 3) & 1;
    const int lm7  = l & 7;
    const int aRowBase = wm * 64 + arow;
    const int bRowBase = wn * 32 + brow;

    int slot = 0;
    for (int kt = 0; kt < kT; kt++) {
        cp_wait1();
        __syncthreads();
        if (kt + 2 < kT) {
            int ps = slot + 2; if (ps >= 3) ps -= 3;
            stage_copy<TERMS>(sbase + ps * STAGE, tid, Ah, Al, lda, Bh, Bl, ldb,
                              (kt + 2) * KC);
        }
        cp_commit();

        const uint32_t sb = sbase + slot * STAGE;
        if (++slot == 3) slot = 0;

#pragma unroll
        for (int k16 = 0; k16 < 4; k16++) {
            // B fragments (shared across tm)
            uint32_t bh[4][2], bl_[4][2];
#pragma unroll
            for (int pr = 0; pr < 2; pr++) {
                uint32_t off = (uint32_t)((bRowBase + pr * 16) * 128)
                             + (uint32_t)(((2 * k16 + c0B) ^ lm7) << 4);
                uint32_t r0, r1, r2, r3;
                ldm_x4(sb + PB_H + off, r0, r1, r2, r3);
                bh[pr * 2][0] = r0; bh[pr * 2][1] = r1;
                bh[pr * 2 + 1][0] = r2; bh[pr * 2 + 1][1] = r3;
                if (TERMS >= 2) {
                    ldm_x4(sb + PB_H + PLANE_B + off, r0, r1, r2, r3);
                    bl_[pr * 2][0] = r0; bl_[pr * 2][1] = r1;
                    bl_[pr * 2 + 1][0] = r2; bl_[pr * 2 + 1][1] = r3;
                }
            }
#pragma unroll
            for (int tm = 0; tm < 4; tm++) {
                uint32_t off = (uint32_t)((aRowBase + tm * 16) * 128)
                             + (uint32_t)(((2 * k16 + c0A) ^ lm7) << 4);
                uint32_t ah[4], al_[4];
                ldm_x4(sb + off, ah[0], ah[1], ah[2], ah[3]);
                if (TERMS == 3)
                    ldm_x4(sb + PLANE_B + off, al_[0], al_[1], al_[2], al_[3]);
#pragma unroll
                for (int tn = 0; tn < 4; tn++) {
                    mma_f16(acc[tm][tn], ah, bh[tn][0], bh[tn][1]);
                    if (TERMS >= 2)
                        mma_f16(acc[tm][tn], ah, bl_[tn][0], bl_[tn][1]);
                    if (TERMS == 3)
                        mma_f16(acc[tm][tn], al_, bh[tn][0], bh[tn][1]);
                }
            }
        }
    }

    // epilogue
    const int g = l >> 2, tg = l & 3;
#pragma unroll
    for (int tm = 0; tm < 4; tm++) {
        const int r0 = wm * 64 + tm * 16 + g;
#pragma unroll
        for (int tn = 0; tn < 4; tn++) {
            const int col = wn * 32 + tn * 8 + tg * 2;
            const float* a = acc[tm][tn];
            if (mode == 1) {
                *(float2*)(Cf + (size_t)r0 * ldc + col) =
                    make_float2(a[0] * scale, a[1] * scale);
                *(float2*)(Cf + (size_t)(r0 + 8) * ldc + col) =
                    make_float2(a[2] * scale, a[3] * scale);
            } else if (mode == 0) {
#pragma unroll
                for (int h = 0; h < 2; h++) {
                    size_t o = (size_t)(r0 + 8 * h) * ldc + col;
                    *(__half2*)(Ch + o) = __halves2half2(
                        __float2half_rn(a[2 * h]), __float2half_rn(a[2 * h + 1]));
                }
            } else {
#pragma unroll
                for (int h = 0; h < 2; h++) {
                    float x0 = a[2 * h], x1 = a[2 * h + 1];
                    fp16 h0 = __float2half_rn(x0);
                    fp16 h1 = __float2half_rn(x1);
                    fp16 l0 = __float2half_rn(x0 - __half2float(h0));
                    fp16 l1 = __float2half_rn(x1 - __half2float(h1));
                    size_t o = (size_t)(r0 + 8 * h) * ldc + col;
                    *(__half2*)(Ch + o) = __halves2half2(h0, h1);
                    *(__half2*)(Cl + o) = __halves2half2(l0, l1);
                }
            }
        }
    }
}

#define SMEM_QKV    (3 * 4 * PLANE_B)   // 196608
#define SMEM_SCORES (3 * 2 * PLANE_B)   // 98304
#define SMEM_PV     (3 * 3 * PLANE_B)   // 147456

// =========================== GEMM kernels =================================
__global__ __launch_bounds__(256, 1)
void k_qkv()
{
    const int z = blockIdx.z;
    const size_t m0 = (size_t)blockIdx.y * 128;
    const size_t n0 = (size_t)blockIdx.x * 128;
    if (z == 2) {   // V: split hi/lo output
        gemm_core<3>(g_Xh + m0 * Dd, g_Xl + m0 * Dd, Dd,
                     g_Wh[2] + n0 * Dd, g_Wl[2] + n0 * Dd, Dd, Dd,
                     nullptr, g_Vh + m0 * Dd + n0, g_Vl + m0 * Dd + n0,
                     Dd, 1.0f, 2);
    } else {        // Q, K: hi-plane only
        fp16* Oh = (z == 0) ? g_Qh : g_Kh;
        gemm_core<3>(g_Xh + m0 * Dd, g_Xl + m0 * Dd, Dd,
                     g_Wh[z] + n0 * Dd, g_Wl[z] + n0 * Dd, Dd, Dd,
                     nullptr, Oh + m0 * Dd + n0, nullptr, Dd, 1.0f, 0);
    }
}

__global__ __launch_bounds__(256, 2)
void k_scores()
{
    const int kt = blockIdx.x, qt = blockIdx.y, b = blockIdx.z;
    if (kt > qt) return;
    const size_t qo = (size_t)b * Sq * Dd + (size_t)qt * 128 * Dd;
    const size_t ko = (size_t)b * Sq * Dd + (size_t)kt * 128 * Dd;
    gemm_core<1>(g_Qh + qo, nullptr, Dd,
                 g_Kh + ko, nullptr, Dd, Dd,
                 g_S + (size_t)b * Sq * Sq + (size_t)qt * 128 * Sq + kt * 128,
                 nullptr, nullptr, Sq, 0.03125f, 1);
}

__global__ __launch_bounds__(256, 1)
void k_pv(float* __restrict__ out)
{
    const int b = blockIdx.z;
    const size_t m0 = (size_t)blockIdx.y * 128;
    const size_t n0 = (size_t)blockIdx.x * 128;
    const size_t po = (size_t)b * Sq * Sq + m0 * Sq;
    const size_t vo = (size_t)b * Sq * Dd + n0 * Sq;
    gemm_core<2>(g_Ph + po, nullptr, Sq,
                 g_Vth + vo, g_Vtl + vo, Sq, (int)(m0 + 128),
                 out + (size_t)b * Sq * Dd + m0 * Dd + n0,
                 nullptr, nullptr, Dd, 1.0f, 1);
}

// =========================== aux kernels ==================================
__global__ __launch_bounds__(256)
void k_splitX(const float* __restrict__ s, fp16* __restrict__ h,
              fp16* __restrict__ l)
{
    int i = blockIdx.x * 256 + threadIdx.x;
    float4 v = ((const float4*)s)[i];
    fp16 h0 = __float2half_rn(v.x), h1 = __float2half_rn(v.y);
    fp16 h2 = __float2half_rn(v.z), h3 = __float2half_rn(v.w);
    fp16 l0 = __float2half_rn(v.x - __half2float(h0));
    fp16 l1 = __float2half_rn(v.y - __half2float(h1));
    fp16 l2 = __float2half_rn(v.z - __half2float(h2));
    fp16 l3 = __float2half_rn(v.w - __half2float(h3));
    ((__half2*)h)[2 * i]     = __halves2half2(h0, h1);
    ((__half2*)h)[2 * i + 1] = __halves2half2(h2, h3);
    ((__half2*)l)[2 * i]     = __halves2half2(l0, l1);
    ((__half2*)l)[2 * i + 1] = __halves2half2(l2, l3);
}

__global__ __launch_bounds__(256)
void k_splitW(const float* __restrict__ wq, const float* __restrict__ wk,
              const float* __restrict__ wv)
{
    const int z = blockIdx.y;
    const float* s = (z == 0) ? wq : (z == 1) ? wk : wv;
    fp16* h = g_Wh[z];
    fp16* l = g_Wl[z];
    int i = blockIdx.x * 256 + threadIdx.x;
    float4 v = ((const float4*)s)[i];
    fp16 h0 = __float2half_rn(v.x), h1 = __float2half_rn(v.y);
    fp16 h2 = __float2half_rn(v.z), h3 = __float2half_rn(v.w);
    fp16 l0 = __float2half_rn(v.x - __half2float(h0));
    fp16 l1 = __float2half_rn(v.y - __half2float(h1));
    fp16 l2 = __float2half_rn(v.z - __half2float(h2));
    fp16 l3 = __float2half_rn(v.w - __half2float(h3));
    ((__half2*)h)[2 * i]     = __halves2half2(h0, h1);
    ((__half2*)h)[2 * i + 1] = __halves2half2(h2, h3);
    ((__half2*)l)[2 * i]     = __halves2half2(l0, l1);
    ((__half2*)l)[2 * i + 1] = __halves2half2(l2, l3);
}

__global__ void k_vtrans()
{
    __shared__ fp16 t[32][33];
    const int zz = blockIdx.z, b = zz >> 1, pl = zz & 1;
    const fp16* V = (pl ? g_Vl : g_Vh) + (size_t)b * Sq * Dd;
    fp16*       T = (pl ? g_Vtl : g_Vth) + (size_t)b * Sq * Dd;
    const int s0 = blockIdx.x * 32, d0 = blockIdx.y * 32;
    const int x = threadIdx.x, y = threadIdx.y;
#pragma unroll
    for (int i = 0; i < 32; i += 8)
        t[y + i][x] = V[(size_t)(s0 + y + i) * Dd + d0 + x];
    __syncthreads();
#pragma unroll
    for (int i = 0; i < 32; i += 8)
        T[(size_t)(d0 + y + i) * Sq + s0 + x] = t[x][y + i];
}

__global__ __launch_bounds__(256)
void k_softmax()
{
    const int q = blockIdx.x, b = blockIdx.y;
    const size_t ro = ((size_t)b * Sq + q) * Sq;
    const float* row = g_S + ro;
    const int len = q + 1;
    const int tid = threadIdx.x;

    __shared__ float buf[Sq];
    __shared__ float red[8];
    __shared__ float bval;

    float m = -3.4e38f;
    for (int i = tid; i < len; i += 256) {
        float v = row[i];
        buf[i] = v;
        m = fmaxf(m, v);
    }
#pragma unroll
    for (int o = 16; o > 0; o >>= 1) m = fmaxf(m, __shfl_xor_sync(0xffffffffu, m, o));
    if ((tid & 31) == 0) red[tid >> 5] = m;
    __syncthreads();
    if (tid == 0) {
        float mm = red[0];
#pragma unroll
        for (int w = 1; w < 8; w++) mm = fmaxf(mm, red[w]);
        bval = mm;
    }
    __syncthreads();
    m = bval;

    float s = 0.f;
    for (int i = tid; i < len; i += 256) {
        float e = __expf(buf[i] - m);
        buf[i] = e;
        s += e;
    }
#pragma unroll
    for (int o = 16; o > 0; o >>= 1) s += __shfl_xor_sync(0xffffffffu, s, o);
    __syncthreads();
    if ((tid & 31) == 0) red[tid >> 5] = s;
    __syncthreads();
    if (tid == 0) {
        float ss = red[0];
#pragma unroll
        for (int w = 1; w < 8; w++) ss += red[w];
        bval = 1.f / ss;
    }
    __syncthreads();
    const float inv = bval;

    for (int i = tid; i < len; i += 256)
        g_Ph[ro + i] = __float2half_rn(buf[i] * inv);
    const int padlen = ((q >> 7) + 1) << 7;
    for (int i = len + tid; i < padlen; i += 256)
        g_Ph[ro + i] = __float2half_rn(0.f);
}

// ===========================================================================
extern "C" void kernel_launch(void* const* d_in, const int* in_sizes, int n_in,
                              void* d_out, int out_size)
{
    const float* X  = (const float*)d_in[0];
    const float* Wq = (const float*)d_in[1];
    const float* Wk = (const float*)d_in[2];
    const float* Wv = (const float*)d_in[3];
    float* out = (float*)d_out;

    cudaFuncSetAttribute(k_qkv,    cudaFuncAttributeMaxDynamicSharedMemorySize, SMEM_QKV);
    cudaFuncSetAttribute(k_scores, cudaFuncAttributeMaxDynamicSharedMemorySize, SMEM_SCORES);
    cudaFuncSetAttribute(k_pv,     cudaFuncAttributeMaxDynamicSharedMemorySize, SMEM_PV);

    fp16 *xh, *xl;
    cudaGetSymbolAddress((void**)&xh, g_Xh);
    cudaGetSymbolAddress((void**)&xl, g_Xl);

    k_splitX<<<MS * Dd / 4 / 256, 256>>>(X, xh, xl);
    k_splitW<<<dim3(Dd * Dd / 4 / 256, 3), 256>>>(Wq, Wk, Wv);

    k_qkv<<<dim3(Dd / 128, MS / 128, 3), 256, SMEM_QKV>>>();
    k_vtrans<<<dim3(Sq / 32, Dd / 32, Bz * 2), dim3(32, 8)>>>();
    k_scores<<<dim3(Sq / 128, Sq / 128, Bz), 256, SMEM_SCORES>>>();
    k_softmax<<<dim3(Sq, Bz), 256>>>();
    k_pv<<<dim3(Dd / 128, Sq / 128, Bz), 256, SMEM_PV>>>(out);
}

// round 7
// speedup vs baseline: 1.9982x; 1.4081x over previous
#include <cuda_runtime.h>
#include <cuda_fp16.h>
#include <cstdint>

#define Bz 4
#define Sq 4096
#define Dd 1024
#define MS (Bz * Sq)

typedef __half fp16;

// ---------------- scratch (device globals; no allocations allowed) --------
__device__ fp16 g_Xh[(size_t)MS * Dd];
__device__ fp16 g_Wh[3][Dd * Dd], g_Wl[3][Dd * Dd];
__device__ fp16 g_Qh[(size_t)MS * Dd];
__device__ fp16 g_Kh[(size_t)MS * Dd];
__device__ fp16 g_Vh[(size_t)MS * Dd];
__device__ fp16 g_Vth[(size_t)MS * Dd];          // V^T: [b][d][s]
__device__ float g_S[(size_t)Bz * Sq * Sq];      // raw scores (fp32)
__device__ fp16 g_Ph[(size_t)Bz * Sq * Sq];      // probs

// =========================== PTX helpers ==================================
__device__ __forceinline__ uint32_t smem_u32(const void* p) {
    uint32_t a;
    asm("{ .reg .u64 t; cvta.to.shared.u64 t, %1; cvt.u32.u64 %0, t; }"
        : "=r"(a) : "l"(p));
    return a;
}
__device__ __forceinline__ void cp16(uint32_t s, const void* g) {
    asm volatile("cp.async.cg.shared.global [%0], [%1], 16;" :: "r"(s), "l"(g));
}
__device__ __forceinline__ void cp_commit() {
    asm volatile("cp.async.commit_group;" ::: "memory");
}
__device__ __forceinline__ void cp_wait1() {
    asm volatile("cp.async.wait_group 1;" ::: "memory");
}
__device__ __forceinline__ void ldm_x4(uint32_t a, uint32_t& r0, uint32_t& r1,
                                       uint32_t& r2, uint32_t& r3) {
    asm volatile("ldmatrix.sync.aligned.m8n8.x4.shared.b16 {%0,%1,%2,%3}, [%4];"
                 : "=r"(r0), "=r"(r1), "=r"(r2), "=r"(r3) : "r"(a));
}
__device__ __forceinline__ void mma_f16(float (&c)[4],
                                        const uint32_t (&a)[4],
                                        uint32_t b0, uint32_t b1) {
    asm volatile("mma.sync.aligned.m16n8k16.row.col.f32.f16.f16.f32 "
                 "{%0,%1,%2,%3}, {%4,%5,%6,%7}, {%8,%9}, {%0,%1,%2,%3};"
                 : "+f"(c[0]), "+f"(c[1]), "+f"(c[2]), "+f"(c[3])
                 : "r"(a[0]), "r"(a[1]), "r"(a[2]), "r"(a[3]), "r"(b0), "r"(b1));
}

// =========================== GEMM core ====================================
// C[128,128] = A[128,kLen] * B[128,kLen]^T, K-major fp16 planes, KC=64,
// 3-stage cp.async, 256 threads, warp grid 2(M) x 4(N), warp tile 64x32.
// TERMS=2: Ah*Bh + Ah*Bl   (planes Ah, Bh, Bl)
// TERMS=1: Ah*Bh           (planes Ah, Bh)
#define KC 64
#define PLANE_B 16384   // one plane: 128 rows x 128 bytes

template <int TERMS>
__device__ __forceinline__ void stage_copy(uint32_t sb, int tid,
    const fp16* __restrict__ Ah, int lda,
    const fp16* __restrict__ Bh, const fp16* __restrict__ Bl, int ldb, int k0)
{
#pragma unroll
    for (int i = 0; i < 4; i++) {
        int q = tid + (i << 8);
        int m = q >> 3, c = q & 7;
        uint32_t so = (uint32_t)(m * 128 + ((c ^ (m & 7)) << 4));
        size_t ga = (size_t)m * lda + k0 + c * 8;
        size_t gb = (size_t)m * ldb + k0 + c * 8;
        cp16(sb + so, Ah + ga);
        cp16(sb + PLANE_B + so, Bh + gb);
        if (TERMS == 2) cp16(sb + 2 * PLANE_B + so, Bl + gb);
    }
}

// mode: 0 = fp16 out (Ch); 1 = fp32 out with scale (Cf)
template <int TERMS>
__device__ __forceinline__ void gemm_core(
    const fp16* __restrict__ Ah, int lda,
    const fp16* __restrict__ Bh, const fp16* __restrict__ Bl, int ldb,
    int kLen,
    float* __restrict__ Cf, fp16* __restrict__ Ch,
    int ldc, float scale, int mode)
{
    const uint32_t STAGE = (uint32_t)(TERMS + 1) * PLANE_B;

    extern __shared__ char dyn[];
    const uint32_t sbase = smem_u32(dyn);
    const int tid = threadIdx.x;
    const int l = tid & 31, wid = tid >> 5;
    const int wm = wid & 1, wn = wid >> 1;
    const int kT = kLen >> 6;   // K tiles of 64

    float acc[4][4][4];
#pragma unroll
    for (int i = 0; i < 4; i++)
#pragma unroll
        for (int j = 0; j < 4; j++)
#pragma unroll
            for (int k = 0; k < 4; k++) acc[i][j][k] = 0.f;

    stage_copy<TERMS>(sbase, tid, Ah, lda, Bh, Bl, ldb, 0);
    cp_commit();
    if (kT > 1) stage_copy<TERMS>(sbase + STAGE, tid, Ah, lda, Bh, Bl, ldb, KC);
    cp_commit();

    const int arow = l & 15;
    const int c0A  = (l >> 4) & 1;
    const int brow = (l & 7) + ((l & 16) >> 1);
    const int c0B  = (l >> 3) & 1;
    const int lm7  = l & 7;
    const int aRowBase = wm * 64 + arow;
    const int bRowBase = wn * 32 + brow;

    int slot = 0;
    for (int kt = 0; kt < kT; kt++) {
        cp_wait1();
        __syncthreads();
        if (kt + 2 < kT) {
            int ps = slot + 2; if (ps >= 3) ps -= 3;
            stage_copy<TERMS>(sbase + ps * STAGE, tid, Ah, lda, Bh, Bl, ldb,
                              (kt + 2) * KC);
        }
        cp_commit();

        const uint32_t sb = sbase + slot * STAGE;
        if (++slot == 3) slot = 0;

#pragma unroll
        for (int k16 = 0; k16 < 4; k16++) {
            uint32_t bh[4][2], bl_[4][2];
#pragma unroll
            for (int pr = 0; pr < 2; pr++) {
                uint32_t off = (uint32_t)((bRowBase + pr * 16) * 128)
                             + (uint32_t)(((2 * k16 + c0B) ^ lm7) << 4);
                uint32_t r0, r1, r2, r3;
                ldm_x4(sb + PLANE_B + off, r0, r1, r2, r3);
                bh[pr * 2][0] = r0; bh[pr * 2][1] = r1;
                bh[pr * 2 + 1][0] = r2; bh[pr * 2 + 1][1] = r3;
                if (TERMS == 2) {
                    ldm_x4(sb + 2 * PLANE_B + off, r0, r1, r2, r3);
                    bl_[pr * 2][0] = r0; bl_[pr * 2][1] = r1;
                    bl_[pr * 2 + 1][0] = r2; bl_[pr * 2 + 1][1] = r3;
                }
            }
#pragma unroll
            for (int tm = 0; tm < 4; tm++) {
                uint32_t off = (uint32_t)((aRowBase + tm * 16) * 128)
                             + (uint32_t)(((2 * k16 + c0A) ^ lm7) << 4);
                uint32_t ah[4];
                ldm_x4(sb + off, ah[0], ah[1], ah[2], ah[3]);
#pragma unroll
                for (int tn = 0; tn < 4; tn++) {
                    mma_f16(acc[tm][tn], ah, bh[tn][0], bh[tn][1]);
                    if (TERMS == 2)
                        mma_f16(acc[tm][tn], ah, bl_[tn][0], bl_[tn][1]);
                }
            }
        }
    }

    // epilogue
    const int g = l >> 2, tg = l & 3;
#pragma unroll
    for (int tm = 0; tm < 4; tm++) {
        const int r0 = wm * 64 + tm * 16 + g;
#pragma unroll
        for (int tn = 0; tn < 4; tn++) {
            const int col = wn * 32 + tn * 8 + tg * 2;
            const float* a = acc[tm][tn];
            if (mode == 1) {
                *(float2*)(Cf + (size_t)r0 * ldc + col) =
                    make_float2(a[0] * scale, a[1] * scale);
                *(float2*)(Cf + (size_t)(r0 + 8) * ldc + col) =
                    make_float2(a[2] * scale, a[3] * scale);
            } else {
#pragma unroll
                for (int h = 0; h < 2; h++) {
                    size_t o = (size_t)(r0 + 8 * h) * ldc + col;
                    *(__half2*)(Ch + o) = __halves2half2(
                        __float2half_rn(a[2 * h]), __float2half_rn(a[2 * h + 1]));
                }
            }
        }
    }
}

#define SMEM_QKV (3 * 3 * PLANE_B)   // 147456
#define SMEM_T1  (3 * 2 * PLANE_B)   // 98304 (scores, pv)

// =========================== GEMM kernels =================================
__global__ __launch_bounds__(256, 1)
void k_qkv()
{
    const int z = blockIdx.z;
    fp16* Oh = (z == 0) ? g_Qh : (z == 1) ? g_Kh : g_Vh;
    const size_t m0 = (size_t)blockIdx.y * 128;
    const size_t n0 = (size_t)blockIdx.x * 128;
    gemm_core<2>(g_Xh + m0 * Dd, Dd,
                 g_Wh[z] + n0 * Dd, g_Wl[z] + n0 * Dd, Dd, Dd,
                 nullptr, Oh + m0 * Dd + n0, Dd, 1.0f, 0);
}

__global__ __launch_bounds__(256, 2)
void k_scores()
{
    const int kt = blockIdx.x, qt = blockIdx.y, b = blockIdx.z;
    if (kt > qt) return;
    const size_t qo = (size_t)b * Sq * Dd + (size_t)qt * 128 * Dd;
    const size_t ko = (size_t)b * Sq * Dd + (size_t)kt * 128 * Dd;
    gemm_core<1>(g_Qh + qo, Dd,
                 g_Kh + ko, nullptr, Dd, Dd,
                 g_S + (size_t)b * Sq * Sq + (size_t)qt * 128 * Sq + kt * 128,
                 nullptr, Sq, 0.03125f, 1);
}

__global__ __launch_bounds__(256, 2)
void k_pv(float* __restrict__ out)
{
    const int b = blockIdx.z;
    const size_t m0 = (size_t)blockIdx.y * 128;
    const size_t n0 = (size_t)blockIdx.x * 128;
    const size_t po = (size_t)b * Sq * Sq + m0 * Sq;
    const size_t vo = (size_t)b * Sq * Dd + n0 * Sq;
    gemm_core<1>(g_Ph + po, Sq,
                 g_Vth + vo, nullptr, Sq, (int)(m0 + 128),
                 out + (size_t)b * Sq * Dd + m0 * Dd + n0,
                 nullptr, Dd, 1.0f, 1);
}

// =========================== aux kernels ==================================
__global__ __launch_bounds__(256)
void k_splitX(const float* __restrict__ s, fp16* __restrict__ h)
{
    int i = blockIdx.x * 256 + threadIdx.x;
    float4 v = ((const float4*)s)[i];
    ((__half2*)h)[2 * i]     = __halves2half2(__float2half_rn(v.x), __float2half_rn(v.y));
    ((__half2*)h)[2 * i + 1] = __halves2half2(__float2half_rn(v.z), __float2half_rn(v.w));
}

__global__ __launch_bounds__(256)
void k_splitW(const float* __restrict__ wq, const float* __restrict__ wk,
              const float* __restrict__ wv)
{
    const int z = blockIdx.y;
    const float* s = (z == 0) ? wq : (z == 1) ? wk : wv;
    fp16* h = g_Wh[z];
    fp16* l = g_Wl[z];
    int i = blockIdx.x * 256 + threadIdx.x;
    float4 v = ((const float4*)s)[i];
    fp16 h0 = __float2half_rn(v.x), h1 = __float2half_rn(v.y);
    fp16 h2 = __float2half_rn(v.z), h3 = __float2half_rn(v.w);
    fp16 l0 = __float2half_rn(v.x - __half2float(h0));
    fp16 l1 = __float2half_rn(v.y - __half2float(h1));
    fp16 l2 = __float2half_rn(v.z - __half2float(h2));
    fp16 l3 = __float2half_rn(v.w - __half2float(h3));
    ((__half2*)h)[2 * i]     = __halves2half2(h0, h1);
    ((__half2*)h)[2 * i + 1] = __halves2half2(h2, h3);
    ((__half2*)l)[2 * i]     = __halves2half2(l0, l1);
    ((__half2*)l)[2 * i + 1] = __halves2half2(l2, l3);
}

__global__ void k_vtrans()
{
    __shared__ fp16 t[32][33];
    const int b = blockIdx.z;
    const fp16* V = g_Vh  + (size_t)b * Sq * Dd;
    fp16*       T = g_Vth + (size_t)b * Sq * Dd;
    const int s0 = blockIdx.x * 32, d0 = blockIdx.y * 32;
    const int x = threadIdx.x, y = threadIdx.y;
#pragma unroll
    for (int i = 0; i < 32; i += 8)
        t[y + i][x] = V[(size_t)(s0 + y + i) * Dd + d0 + x];
    __syncthreads();
#pragma unroll
    for (int i = 0; i < 32; i += 8)
        T[(size_t)(d0 + y + i) * Sq + s0 + x] = t[x][y + i];
}

__global__ __launch_bounds__(256)
void k_softmax()
{
    const int q = blockIdx.x, b = blockIdx.y;
    const size_t ro = ((size_t)b * Sq + q) * Sq;
    const float* row = g_S + ro;
    const int len = q + 1;
    const int tid = threadIdx.x;

    __shared__ float buf[Sq];
    __shared__ float red[8];
    __shared__ float bval;

    float m = -3.4e38f;
    for (int i = tid; i < len; i += 256) {
        float v = row[i];
        buf[i] = v;
        m = fmaxf(m, v);
    }
#pragma unroll
    for (int o = 16; o > 0; o >>= 1) m = fmaxf(m, __shfl_xor_sync(0xffffffffu, m, o));
    if ((tid & 31) == 0) red[tid >> 5] = m;
    __syncthreads();
    if (tid == 0) {
        float mm = red[0];
#pragma unroll
        for (int w = 1; w < 8; w++) mm = fmaxf(mm, red[w]);
        bval = mm;
    }
    __syncthreads();
    m = bval;

    float s = 0.f;
    for (int i = tid; i < len; i += 256) {
        float e = __expf(buf[i] - m);
        buf[i] = e;
        s += e;
    }
#pragma unroll
    for (int o = 16; o > 0; o >>= 1) s += __shfl_xor_sync(0xffffffffu, s, o);
    __syncthreads();
    if ((tid & 31) == 0) red[tid >> 5] = s;
    __syncthreads();
    if (tid == 0) {
        float ss = red[0];
#pragma unroll
        for (int w = 1; w < 8; w++) ss += red[w];
        bval = 1.f / ss;
    }
    __syncthreads();
    const float inv = bval;

    for (int i = tid; i < len; i += 256)
        g_Ph[ro + i] = __float2half_rn(buf[i] * inv);
    const int padlen = ((q >> 7) + 1) << 7;
    for (int i = len + tid; i < padlen; i += 256)
        g_Ph[ro + i] = __float2half_rn(0.f);
}

// ===========================================================================
extern "C" void kernel_launch(void* const* d_in, const int* in_sizes, int n_in,
                              void* d_out, int out_size)
{
    const float* X  = (const float*)d_in[0];
    const float* Wq = (const float*)d_in[1];
    const float* Wk = (const float*)d_in[2];
    const float* Wv = (const float*)d_in[3];
    float* out = (float*)d_out;

    cudaFuncSetAttribute(k_qkv,    cudaFuncAttributeMaxDynamicSharedMemorySize, SMEM_QKV);
    cudaFuncSetAttribute(k_scores, cudaFuncAttributeMaxDynamicSharedMemorySize, SMEM_T1);
    cudaFuncSetAttribute(k_pv,     cudaFuncAttributeMaxDynamicSharedMemorySize, SMEM_T1);

    fp16* xh;
    cudaGetSymbolAddress((void**)&xh, g_Xh);

    k_splitX<<<MS * Dd / 4 / 256, 256>>>(X, xh);
    k_splitW<<<dim3(Dd * Dd / 4 / 256, 3), 256>>>(Wq, Wk, Wv);

    k_qkv<<<dim3(Dd / 128, MS / 128, 3), 256, SMEM_QKV>>>();
    k_vtrans<<<dim3(Sq / 32, Dd / 32, Bz), dim3(32, 8)>>>();
    k_scores<<<dim3(Sq / 128, Sq / 128, Bz), 256, SMEM_T1>>>();
    k_softmax<<<dim3(Sq, Bz), 256>>>();
    k_pv<<<dim3(Dd / 128, Sq / 128, Bz), 256, SMEM_T1>>>(out);
}

// round 8
// speedup vs baseline: 2.7205x; 1.3614x over previous
#include <cuda_runtime.h>
#include <cuda_fp16.h>
#include <cstdint>

#define Bz 4
#define Sq 4096
#define Dd 1024
#define MS (Bz * Sq)

typedef __half fp16;

// ---------------- scratch (device globals; no allocations allowed) --------
__device__ fp16 g_Xh[(size_t)MS * Dd];
__device__ fp16 g_Wh[3][Dd * Dd];
__device__ fp16 g_Qh[(size_t)MS * Dd];
__device__ fp16 g_Kh[(size_t)MS * Dd];
__device__ fp16 g_Vh[(size_t)MS * Dd];
__device__ fp16 g_Vth[(size_t)MS * Dd];          // V^T: [b][d][s]
__device__ fp16 g_S[(size_t)Bz * Sq * Sq];       // scaled scores (fp16)
__device__ fp16 g_Ph[(size_t)Bz * Sq * Sq];      // probs

// =========================== PTX helpers ==================================
__device__ __forceinline__ uint32_t smem_u32(const void* p) {
    uint32_t a;
    asm("{ .reg .u64 t; cvta.to.shared.u64 t, %1; cvt.u32.u64 %0, t; }"
        : "=r"(a) : "l"(p));
    return a;
}
__device__ __forceinline__ void cp16(uint32_t s, const void* g) {
    asm volatile("cp.async.cg.shared.global [%0], [%1], 16;" :: "r"(s), "l"(g));
}
__device__ __forceinline__ void cp_commit() {
    asm volatile("cp.async.commit_group;" ::: "memory");
}
__device__ __forceinline__ void cp_wait1() {
    asm volatile("cp.async.wait_group 1;" ::: "memory");
}
__device__ __forceinline__ void ldm_x4(uint32_t a, uint32_t& r0, uint32_t& r1,
                                       uint32_t& r2, uint32_t& r3) {
    asm volatile("ldmatrix.sync.aligned.m8n8.x4.shared.b16 {%0,%1,%2,%3}, [%4];"
                 : "=r"(r0), "=r"(r1), "=r"(r2), "=r"(r3) : "r"(a));
}
__device__ __forceinline__ void mma_f16(float (&c)[4],
                                        const uint32_t (&a)[4],
                                        uint32_t b0, uint32_t b1) {
    asm volatile("mma.sync.aligned.m16n8k16.row.col.f32.f16.f16.f32 "
                 "{%0,%1,%2,%3}, {%4,%5,%6,%7}, {%8,%9}, {%0,%1,%2,%3};"
                 : "+f"(c[0]), "+f"(c[1]), "+f"(c[2]), "+f"(c[3])
                 : "r"(a[0]), "r"(a[1]), "r"(a[2]), "r"(a[3]), "r"(b0), "r"(b1));
}

// =========================== GEMM core ====================================
// C[128,128] = A[128,kLen] * B[128,kLen]^T, K-major fp16 planes, KC=64,
// 3-stage cp.async, 256 threads, warp grid 2(M) x 4(N), warp tile 64x32.
// All stages 1-term: Ah*Bh. Stage = 2 planes x 16KB = 32KB -> 96KB, 2 CTA/SM.
#define KC 64
#define PLANE_B 16384
#define STAGE   (2 * PLANE_B)
#define SMEM_G  (3 * STAGE)     // 98304

__device__ __forceinline__ void stage_copy(uint32_t sb, int tid,
    const fp16* __restrict__ Ah, int lda,
    const fp16* __restrict__ Bh, int ldb, int k0)
{
#pragma unroll
    for (int i = 0; i < 4; i++) {
        int q = tid + (i << 8);
        int m = q >> 3, c = q & 7;
        uint32_t so = (uint32_t)(m * 128 + ((c ^ (m & 7)) << 4));
        cp16(sb + so,           Ah + (size_t)m * lda + k0 + c * 8);
        cp16(sb + PLANE_B + so, Bh + (size_t)m * ldb + k0 + c * 8);
    }
}

// mode: 0 = fp16 out with scale (Ch); 1 = fp32 out with scale (Cf)
__device__ __forceinline__ void gemm_core(
    const fp16* __restrict__ Ah, int lda,
    const fp16* __restrict__ Bh, int ldb,
    int kLen,
    float* __restrict__ Cf, fp16* __restrict__ Ch,
    int ldc, float scale, int mode)
{
    extern __shared__ char dyn[];
    const uint32_t sbase = smem_u32(dyn);
    const int tid = threadIdx.x;
    const int l = tid & 31, wid = tid >> 5;
    const int wm = wid & 1, wn = wid >> 1;
    const int kT = kLen >> 6;

    float acc[4][4][4];
#pragma unroll
    for (int i = 0; i < 4; i++)
#pragma unroll
        for (int j = 0; j < 4; j++)
#pragma unroll
            for (int k = 0; k < 4; k++) acc[i][j][k] = 0.f;

    stage_copy(sbase, tid, Ah, lda, Bh, ldb, 0);
    cp_commit();
    if (kT > 1) stage_copy(sbase + STAGE, tid, Ah, lda, Bh, ldb, KC);
    cp_commit();

    const int arow = l & 15;
    const int c0A  = (l >> 4) & 1;
    const int brow = (l & 7) + ((l & 16) >> 1);
    const int c0B  = (l >> 3) & 1;
    const int lm7  = l & 7;
    const int aRowBase = wm * 64 + arow;
    const int bRowBase = wn * 32 + brow;

    int slot = 0;
    for (int kt = 0; kt < kT; kt++) {
        cp_wait1();
        __syncthreads();
        if (kt + 2 < kT) {
            int ps = slot + 2; if (ps >= 3) ps -= 3;
            stage_copy(sbase + ps * STAGE, tid, Ah, lda, Bh, ldb, (kt + 2) * KC);
        }
        cp_commit();

        const uint32_t sb = sbase + slot * STAGE;
        if (++slot == 3) slot = 0;

#pragma unroll
        for (int k16 = 0; k16 < 4; k16++) {
            uint32_t bh[4][2];
#pragma unroll
            for (int pr = 0; pr < 2; pr++) {
                uint32_t off = (uint32_t)((bRowBase + pr * 16) * 128)
                             + (uint32_t)(((2 * k16 + c0B) ^ lm7) << 4);
                uint32_t r0, r1, r2, r3;
                ldm_x4(sb + PLANE_B + off, r0, r1, r2, r3);
                bh[pr * 2][0] = r0; bh[pr * 2][1] = r1;
                bh[pr * 2 + 1][0] = r2; bh[pr * 2 + 1][1] = r3;
            }
#pragma unroll
            for (int tm = 0; tm < 4; tm++) {
                uint32_t off = (uint32_t)((aRowBase + tm * 16) * 128)
                             + (uint32_t)(((2 * k16 + c0A) ^ lm7) << 4);
                uint32_t ah[4];
                ldm_x4(sb + off, ah[0], ah[1], ah[2], ah[3]);
#pragma unroll
                for (int tn = 0; tn < 4; tn++)
                    mma_f16(acc[tm][tn], ah, bh[tn][0], bh[tn][1]);
            }
        }
    }

    // epilogue
    const int g = l >> 2, tg = l & 3;
#pragma unroll
    for (int tm = 0; tm < 4; tm++) {
        const int r0 = wm * 64 + tm * 16 + g;
#pragma unroll
        for (int tn = 0; tn < 4; tn++) {
            const int col = wn * 32 + tn * 8 + tg * 2;
            const float* a = acc[tm][tn];
            if (mode == 1) {
                *(float2*)(Cf + (size_t)r0 * ldc + col) =
                    make_float2(a[0] * scale, a[1] * scale);
                *(float2*)(Cf + (size_t)(r0 + 8) * ldc + col) =
                    make_float2(a[2] * scale, a[3] * scale);
            } else {
#pragma unroll
                for (int h = 0; h < 2; h++) {
                    size_t o = (size_t)(r0 + 8 * h) * ldc + col;
                    *(__half2*)(Ch + o) = __halves2half2(
                        __float2half_rn(a[2 * h] * scale),
                        __float2half_rn(a[2 * h + 1] * scale));
                }
            }
        }
    }
}

// =========================== GEMM kernels =================================
__global__ __launch_bounds__(256, 2)
void k_qkv()
{
    const int z = blockIdx.z;
    fp16* Oh = (z == 0) ? g_Qh : (z == 1) ? g_Kh : g_Vh;
    const size_t m0 = (size_t)blockIdx.y * 128;
    const size_t n0 = (size_t)blockIdx.x * 128;
    gemm_core(g_Xh + m0 * Dd, Dd, g_Wh[z] + n0 * Dd, Dd, Dd,
              nullptr, Oh + m0 * Dd + n0, Dd, 1.0f, 0);
}

__global__ __launch_bounds__(256, 2)
void k_scores()
{
    const int kt = blockIdx.x, qt = blockIdx.y, b = blockIdx.z;
    if (kt > qt) return;
    const size_t qo = (size_t)b * Sq * Dd + (size_t)qt * 128 * Dd;
    const size_t ko = (size_t)b * Sq * Dd + (size_t)kt * 128 * Dd;
    gemm_core(g_Qh + qo, Dd, g_Kh + ko, Dd, Dd,
              nullptr,
              g_S + (size_t)b * Sq * Sq + (size_t)qt * 128 * Sq + kt * 128,
              Sq, 0.03125f, 0);
}

__global__ __launch_bounds__(256, 2)
void k_pv(float* __restrict__ out)
{
    const int b = blockIdx.z;
    const size_t m0 = (size_t)blockIdx.y * 128;
    const size_t n0 = (size_t)blockIdx.x * 128;
    const size_t po = (size_t)b * Sq * Sq + m0 * Sq;
    const size_t vo = (size_t)b * Sq * Dd + n0 * Sq;
    gemm_core(g_Ph + po, Sq, g_Vth + vo, Sq, (int)(m0 + 128),
              out + (size_t)b * Sq * Dd + m0 * Dd + n0,
              nullptr, Dd, 1.0f, 1);
}

// =========================== aux kernels ==================================
__global__ __launch_bounds__(256)
void k_cvtX(const float* __restrict__ s, fp16* __restrict__ h)
{
    int i = blockIdx.x * 256 + threadIdx.x;
    float4 v = ((const float4*)s)[i];
    ((__half2*)h)[2 * i]     = __halves2half2(__float2half_rn(v.x), __float2half_rn(v.y));
    ((__half2*)h)[2 * i + 1] = __halves2half2(__float2half_rn(v.z), __float2half_rn(v.w));
}

__global__ __launch_bounds__(256)
void k_cvtW(const float* __restrict__ wq, const float* __restrict__ wk,
            const float* __restrict__ wv)
{
    const int z = blockIdx.y;
    const float* s = (z == 0) ? wq : (z == 1) ? wk : wv;
    fp16* h = g_Wh[z];
    int i = blockIdx.x * 256 + threadIdx.x;
    float4 v = ((const float4*)s)[i];
    ((__half2*)h)[2 * i]     = __halves2half2(__float2half_rn(v.x), __float2half_rn(v.y));
    ((__half2*)h)[2 * i + 1] = __halves2half2(__float2half_rn(v.z), __float2half_rn(v.w));
}

__global__ void k_vtrans()
{
    __shared__ fp16 t[32][33];
    const int b = blockIdx.z;
    const fp16* V = g_Vh  + (size_t)b * Sq * Dd;
    fp16*       T = g_Vth + (size_t)b * Sq * Dd;
    const int s0 = blockIdx.x * 32, d0 = blockIdx.y * 32;
    const int x = threadIdx.x, y = threadIdx.y;
#pragma unroll
    for (int i = 0; i < 32; i += 8)
        t[y + i][x] = V[(size_t)(s0 + y + i) * Dd + d0 + x];
    __syncthreads();
#pragma unroll
    for (int i = 0; i < 32; i += 8)
        T[(size_t)(d0 + y + i) * Sq + s0 + x] = t[x][y + i];
}

__global__ __launch_bounds__(256)
void k_softmax()
{
    const int q = blockIdx.x, b = blockIdx.y;
    const size_t ro = ((size_t)b * Sq + q) * Sq;
    const fp16* row = g_S + ro;
    const int len = q + 1;
    const int tid = threadIdx.x;

    __shared__ float buf[Sq];
    __shared__ float red[8];
    __shared__ float bval;

    float m = -3.4e38f;
    for (int i = tid; i < len; i += 256) {
        float v = __half2float(row[i]);
        buf[i] = v;
        m = fmaxf(m, v);
    }
#pragma unroll
    for (int o = 16; o > 0; o >>= 1) m = fmaxf(m, __shfl_xor_sync(0xffffffffu, m, o));
    if ((tid & 31) == 0) red[tid >> 5] = m;
    __syncthreads();
    if (tid == 0) {
        float mm = red[0];
#pragma unroll
        for (int w = 1; w < 8; w++) mm = fmaxf(mm, red[w]);
        bval = mm;
    }
    __syncthreads();
    m = bval;

    float s = 0.f;
    for (int i = tid; i < len; i += 256) {
        float e = __expf(buf[i] - m);
        buf[i] = e;
        s += e;
    }
#pragma unroll
    for (int o = 16; o > 0; o >>= 1) s += __shfl_xor_sync(0xffffffffu, s, o);
    __syncthreads();
    if ((tid & 31) == 0) red[tid >> 5] = s;
    __syncthreads();
    if (tid == 0) {
        float ss = red[0];
#pragma unroll
        for (int w = 1; w < 8; w++) ss += red[w];
        bval = 1.f / ss;
    }
    __syncthreads();
    const float inv = bval;

    for (int i = tid; i < len; i += 256)
        g_Ph[ro + i] = __float2half_rn(buf[i] * inv);
    const int padlen = ((q >> 7) + 1) << 7;
    for (int i = len + tid; i < padlen; i += 256)
        g_Ph[ro + i] = __float2half_rn(0.f);
}

// ===========================================================================
extern "C" void kernel_launch(void* const* d_in, const int* in_sizes, int n_in,
                              void* d_out, int out_size)
{
    const float* X  = (const float*)d_in[0];
    const float* Wq = (const float*)d_in[1];
    const float* Wk = (const float*)d_in[2];
    const float* Wv = (const float*)d_in[3];
    float* out = (float*)d_out;

    cudaFuncSetAttribute(k_qkv,    cudaFuncAttributeMaxDynamicSharedMemorySize, SMEM_G);
    cudaFuncSetAttribute(k_scores, cudaFuncAttributeMaxDynamicSharedMemorySize, SMEM_G);
    cudaFuncSetAttribute(k_pv,     cudaFuncAttributeMaxDynamicSharedMemorySize, SMEM_G);

    fp16* xh;
    cudaGetSymbolAddress((void**)&xh, g_Xh);

    k_cvtX<<<MS * Dd / 4 / 256, 256>>>(X, xh);
    k_cvtW<<<dim3(Dd * Dd / 4 / 256, 3), 256>>>(Wq, Wk, Wv);

    k_qkv<<<dim3(Dd / 128, MS / 128, 3), 256, SMEM_G>>>();
    k_vtrans<<<dim3(Sq / 32, Dd / 32, Bz), dim3(32, 8)>>>();
    k_scores<<<dim3(Sq / 128, Sq / 128, Bz), 256, SMEM_G>>>();
    k_softmax<<<dim3(Sq, Bz), 256>>>();
    k_pv<<<dim3(Dd / 128, Sq / 128, Bz), 256, SMEM_G>>>(out);
}